// round 4
// baseline (speedup 1.0000x reference)
#include <cuda_runtime.h>
#include <stdint.h>

// LengthRegulator: out[n, t, :] = x[n, searchsorted(csum[n], t, 'right'), :]
// for t < total[n], else 0.  mel_pos = [1..T] appended after the frames.
//
// Layout (validated via out_size divisibility, N*C = 24576):
//   case A: [ out: N*T*C f32 ][ mel_pos: T f32 ]
//   case B: [ out: N*T*C f32 ][ mel_pos: T i64 ]
//
// Single fused kernel: warp-shuffle prefix scan (3 barriers), one warp does
// the 32 binary searches, warps copy whole frames with lane-contiguous
// float4 stores. Blocks with blockIdx.y==0 also emit mel_pos (no 2nd launch).

#define L_LEN   256
#define THREADS 256
#define FRAMES  32

__global__ __launch_bounds__(THREADS)
void lr_fused_kernel(const float* __restrict__ x,
                     const int* __restrict__ dur,
                     float* __restrict__ out,
                     float* __restrict__ mp,
                     int T, int C, int mel_is_i64)
{
    const int n    = blockIdx.y;
    const int t0   = blockIdx.x * FRAMES;
    const int tid  = threadIdx.x;
    const int wid  = tid >> 5;
    const int lane = tid & 31;
    const int vec  = C >> 2;               // float4 per frame (96 for C=384)

    __shared__ int csum[L_LEN];
    __shared__ int wsum[8];
    __shared__ int fidx[FRAMES];

    // ---- mel_pos (blocks in row 0 only; independent of everything below) ----
    if (blockIdx.y == 0 && tid < FRAMES) {
        int t = t0 + tid;
        if (t < T) {
            if (mel_is_i64) ((long long*)mp)[t] = (long long)(t + 1);
            else            mp[t] = (float)(t + 1);
        }
    }

    // ---- inclusive prefix sum via warp shuffles (3 barriers total) ----
    int v = dur[n * L_LEN + tid];
    #pragma unroll
    for (int off = 1; off < 32; off <<= 1) {
        int u = __shfl_up_sync(0xFFFFFFFFu, v, off);
        if (lane >= off) v += u;
    }
    if (lane == 31) wsum[wid] = v;
    __syncthreads();
    if (wid == 0 && lane < 8) {
        int s = wsum[lane];
        #pragma unroll
        for (int off = 1; off < 8; off <<= 1) {
            int u = __shfl_up_sync(0xFFu, s, off);
            if (lane >= off) s += u;
        }
        wsum[lane] = s;
    }
    __syncthreads();
    csum[tid] = v + (wid > 0 ? wsum[wid - 1] : 0);
    __syncthreads();

    const int total = csum[L_LEN - 1];

    // ---- one warp: binary search source row for each of the 32 frames ----
    if (wid == 0) {
        int t  = t0 + lane;
        int id = -1;
        if (t < T && t < total) {
            int lo = 0, hi = L_LEN;
            #pragma unroll
            while (lo < hi) {
                int mid = (lo + hi) >> 1;
                if (csum[mid] > t) hi = mid; else lo = mid + 1;
            }
            id = (lo < L_LEN) ? lo : (L_LEN - 1);
        }
        fidx[lane] = id;
    }
    __syncthreads();

    // ---- copy: each warp owns FRAMES/8 = 4 frames, lane-contiguous float4 ----
    const float4* xv = (const float4*)(x + (size_t)n * L_LEN * C);
    float4*       ov = (float4*)(out + ((size_t)n * T + t0) * C);
    const float4  z  = make_float4(0.f, 0.f, 0.f, 0.f);

    #pragma unroll
    for (int j = 0; j < FRAMES / 8; j++) {
        const int f = wid * (FRAMES / 8) + j;
        const int t = t0 + f;
        if (t < T) {
            const int id = fidx[f];
            float4* dst = ov + (size_t)f * vec;
            if (id >= 0) {
                const float4* src = xv + (size_t)id * vec;
                #pragma unroll 3
                for (int c = lane; c < vec; c += 32)
                    dst[c] = __ldg(&src[c]);
            } else {
                #pragma unroll 3
                for (int c = lane; c < vec; c += 32)
                    dst[c] = z;
            }
        }
    }
}

extern "C" void kernel_launch(void* const* d_in, const int* in_sizes, int n_in,
                              void* d_out, int out_size)
{
    const float* x   = (const float*)d_in[0];
    const int*   dur = (const int*)d_in[1];

    const int NL = in_sizes[1];            // N * L
    const int N  = NL / L_LEN;             // L fixed at 256
    const int C  = in_sizes[0] / NL;       // 384

    const long long S    = (long long)out_size;
    const long long base = (long long)N * C;

    int T;
    int mel_is_i64 = 0;
    if (S % (base + 1) == 0) {
        T = (int)(S / (base + 1));         // case A: mel_pos as f32
    } else if (S % (base + 2) == 0) {
        T = (int)(S / (base + 2));         // case B: mel_pos as i64
        mel_is_i64 = 1;
    } else {
        T = (int)(S / base);               // fallback: frames only
    }

    float* out  = (float*)d_out;
    float* tail = out + (size_t)N * T * C;

    dim3 grid((T + FRAMES - 1) / FRAMES, N);
    lr_fused_kernel<<<grid, THREADS>>>(x, dur, out, tail, T, C, mel_is_i64);
}

// round 5
// speedup vs baseline: 1.2655x; 1.2655x over previous
#include <cuda_runtime.h>
#include <stdint.h>

// LengthRegulator: out[n, t, :] = x[n, searchsorted(csum[n], t, 'right'), :]
// for t < total[n], else 0.  mel_pos = [1..T] appended after the frames.
//
// Layout (validated via out_size divisibility, N*C = 24576):
//   case A: [ out: N*T*C f32 ][ mel_pos: T f32 ]
//   case B: [ out: N*T*C f32 ][ mel_pos: T i64 ]
//
// R5 design: l1tex was the bottleneck (71.8%) because gather loads duplicate
// store traffic through the same pipe. Each thread owns a fixed channel chunk
// (c = tid % 96) and walks 8 consecutive frames, caching its float4 of the
// source row in a register — consecutive frames share a source row ~88% of
// the time (mean duration 8.5), cutting load wavefronts ~4.4x.

#define L_LEN     256
#define THREADS   288          // 9 warps = 3 frame-groups x 96 channel threads
#define FRAMES    24           // 3 groups x 8 consecutive frames
#define FPG       8            // frames per group (walked by one thread)

__global__ __launch_bounds__(THREADS)
void lr_fused_kernel(const float* __restrict__ x,
                     const int* __restrict__ dur,
                     float* __restrict__ out,
                     float* __restrict__ mp,
                     int T, int C, int mel_is_i64)
{
    const int n    = blockIdx.y;
    const int t0   = blockIdx.x * FRAMES;
    const int tid  = threadIdx.x;
    const int wid  = tid >> 5;
    const int lane = tid & 31;
    const int vec  = C >> 2;               // 96 float4 per frame

    __shared__ int csum[L_LEN];
    __shared__ int wsum[8];
    __shared__ int fidx[FRAMES];

    // ---- mel_pos (row-0 blocks only; independent work) ----
    if (blockIdx.y == 0 && tid < FRAMES) {
        int t = t0 + tid;
        if (t < T) {
            if (mel_is_i64) ((long long*)mp)[t] = (long long)(t + 1);
            else            mp[t] = (float)(t + 1);
        }
    }

    // ---- inclusive prefix sum of durations (shuffle scan, warps 0..7) ----
    int v = 0;
    if (tid < L_LEN) {
        v = dur[n * L_LEN + tid];
        #pragma unroll
        for (int off = 1; off < 32; off <<= 1) {
            int u = __shfl_up_sync(0xFFFFFFFFu, v, off);
            if (lane >= off) v += u;
        }
        if (lane == 31) wsum[wid] = v;
    }
    __syncthreads();
    if (wid == 0 && lane < 8) {
        int s = wsum[lane];
        #pragma unroll
        for (int off = 1; off < 8; off <<= 1) {
            int u = __shfl_up_sync(0xFFu, s, off);
            if (lane >= off) s += u;
        }
        wsum[lane] = s;
    }
    __syncthreads();
    if (tid < L_LEN) csum[tid] = v + (wid > 0 ? wsum[wid - 1] : 0);
    __syncthreads();

    const int total = csum[L_LEN - 1];

    // ---- binary search source row for each frame (first 24 threads) ----
    if (tid < FRAMES) {
        int t  = t0 + tid;
        int id = -1;
        if (t < T && t < total) {
            int lo = 0, hi = L_LEN;
            while (lo < hi) {
                int mid = (lo + hi) >> 1;
                if (csum[mid] > t) hi = mid; else lo = mid + 1;
            }
            id = (lo < L_LEN) ? lo : (L_LEN - 1);
        }
        fidx[tid] = id;
    }
    __syncthreads();

    // ---- copy with register-cached source row ----
    // thread -> (group g, channel c); walks FPG consecutive frames with same c,
    // reloading its float4 only when the source id changes (warp-uniform test).
    const int g = tid / 96;                // 0..2
    const int c = tid - g * 96;            // 0..95

    const float4* xv = (const float4*)(x + (size_t)n * L_LEN * C);
    float4*       ov = (float4*)(out + ((size_t)n * T + t0) * C);
    const float4  z  = make_float4(0.f, 0.f, 0.f, 0.f);

    int    cur = -2;                       // cached source id (-2 = none)
    float4 val = z;

    const int fbase = g * FPG;
    #pragma unroll
    for (int i = 0; i < FPG; i++) {
        const int f = fbase + i;
        const int t = t0 + f;
        if (t >= T) break;
        const int id = fidx[f];
        if (id != cur) {                   // warp-uniform branch
            val = (id >= 0) ? __ldg(&xv[(size_t)id * 96 + c]) : z;
            cur = id;
        }
        ov[(size_t)f * 96 + c] = val;
    }
}

extern "C" void kernel_launch(void* const* d_in, const int* in_sizes, int n_in,
                              void* d_out, int out_size)
{
    const float* x   = (const float*)d_in[0];
    const int*   dur = (const int*)d_in[1];

    const int NL = in_sizes[1];            // N * L
    const int N  = NL / L_LEN;             // L fixed at 256
    const int C  = in_sizes[0] / NL;       // 384

    const long long S    = (long long)out_size;
    const long long base = (long long)N * C;

    int T;
    int mel_is_i64 = 0;
    if (S % (base + 1) == 0) {
        T = (int)(S / (base + 1));         // case A: mel_pos as f32
    } else if (S % (base + 2) == 0) {
        T = (int)(S / (base + 2));         // case B: mel_pos as i64
        mel_is_i64 = 1;
    } else {
        T = (int)(S / base);               // fallback: frames only
    }

    float* out  = (float*)d_out;
    float* tail = out + (size_t)N * T * C;

    dim3 grid((T + FRAMES - 1) / FRAMES, N);
    lr_fused_kernel<<<grid, THREADS>>>(x, dur, out, tail, T, C, mel_is_i64);
}